// round 15
// baseline (speedup 1.0000x reference)
#include <cuda_runtime.h>
#include <cuda_bf16.h>
#include <cstdint>

// ---------------------------------------------------------------------------
// HeteroEdgePromptPlus — folded formulation.
//   logits[e,k] = srcLogits[src(e),k] + dstLogits[dst(e),k]   (bias folded)
//   b = softmax(leaky_relu(logits)) ; out[e] = b @ A
// Edge kernel: validated round-14 fused pipeline (16 edges/stage).
// Node kernel: 4 nodes/thread, 256 nodes/block, f32x2 inner loop.
// ---------------------------------------------------------------------------

#define MAXN 50000
typedef unsigned long long ull;

// fold outputs in ONE buffer (single memset): Mp | Ma | cp | ca
__device__ float g_fold[48 * 256 + 16 * 128 + 48 + 16];
#define G_MP (g_fold)
#define G_MA (g_fold + 12288)
#define G_CP (g_fold + 14336)
#define G_CA (g_fold + 14384)
__device__ float g_paperL[(size_t)MAXN * 48];
__device__ float g_authorL[(size_t)MAXN * 16];

// ---- f32x2 packed helpers (Blackwell) -------------------------------------
__device__ __forceinline__ ull pk2(float x, float y) {
    ull r;
    asm("mov.b64 %0, {%1, %2};" : "=l"(r) : "f"(x), "f"(y));
    return r;
}
__device__ __forceinline__ void upk(ull v, float& x, float& y) {
    asm("mov.b64 {%0, %1}, %2;" : "=f"(x), "=f"(y) : "l"(v));
}
__device__ __forceinline__ void fma2(ull& d, ull a, ull b) {
    asm("fma.rn.f32x2 %0, %1, %2, %0;" : "+l"(d) : "l"(a), "l"(b));
}
__device__ __forceinline__ void st4cs(float* p, ull a, ull b) {
    float x, y, z, w;
    upk(a, x, y);
    upk(b, z, w);
    asm volatile("st.global.cs.v4.f32 [%0], {%1, %2, %3, %4};"
                 :: "l"(p), "f"(x), "f"(y), "f"(z), "f"(w) : "memory");
}

// ---------------------------------------------------------------------------
// Kernel 1: fold weights. grid = (64, 4): x = output row, y = p-chunk of 32.
// ---------------------------------------------------------------------------
__global__ void fold_kernel(const float* __restrict__ Wp_p,
                            const float* __restrict__ bp_p,
                            const float* __restrict__ Wp_a,
                            const float* __restrict__ bp_a,
                            const float* __restrict__ Ws_w,
                            const float* __restrict__ bs_w,
                            const float* __restrict__ Ws_c,
                            const float* __restrict__ bs_c) {
    const int b = blockIdx.x, t = threadIdx.x;
    const int pBeg = blockIdx.y * 32, pEnd = pBeg + 32;
    if (b < 48) {
        int k = b & 15, grp = b >> 4;
        const float* wrow = (grp == 0) ? (Ws_w + k * 256 + 128)
                          : (grp == 1) ? (Ws_c + k * 256)
                                       : (Ws_c + k * 256 + 128);
        float a0 = 0.f, a1 = 0.f, a2 = 0.f, a3 = 0.f;
        #pragma unroll
        for (int p = pBeg; p < pEnd; p += 4) {
            a0 = fmaf(__ldg(&wrow[p + 0]), __ldg(&Wp_p[(p + 0) * 256 + t]), a0);
            a1 = fmaf(__ldg(&wrow[p + 1]), __ldg(&Wp_p[(p + 1) * 256 + t]), a1);
            a2 = fmaf(__ldg(&wrow[p + 2]), __ldg(&Wp_p[(p + 2) * 256 + t]), a2);
            a3 = fmaf(__ldg(&wrow[p + 3]), __ldg(&Wp_p[(p + 3) * 256 + t]), a3);
        }
        atomicAdd(&G_MP[b * 256 + t], (a0 + a1) + (a2 + a3));
        if (t == 0) {
            float c0 = (blockIdx.y == 0)
                           ? ((grp == 0) ? bs_w[k] : (grp == 2) ? bs_c[k] : 0.f)
                           : 0.f;
            float c1 = 0.f, c2 = 0.f, c3 = 0.f;
            #pragma unroll
            for (int p = pBeg; p < pEnd; p += 4) {
                c0 = fmaf(wrow[p + 0], bp_p[p + 0], c0);
                c1 = fmaf(wrow[p + 1], bp_p[p + 1], c1);
                c2 = fmaf(wrow[p + 2], bp_p[p + 2], c2);
                c3 = fmaf(wrow[p + 3], bp_p[p + 3], c3);
            }
            atomicAdd(&G_CP[b], (c0 + c1) + (c2 + c3));
        }
    } else {
        int k = b - 48;
        if (t < 128) {
            const float* wrow = Ws_w + k * 256;  // src half -> author
            float a0 = 0.f, a1 = 0.f, a2 = 0.f, a3 = 0.f;
            #pragma unroll
            for (int p = pBeg; p < pEnd; p += 4) {
                a0 = fmaf(__ldg(&wrow[p + 0]), __ldg(&Wp_a[(p + 0) * 128 + t]), a0);
                a1 = fmaf(__ldg(&wrow[p + 1]), __ldg(&Wp_a[(p + 1) * 128 + t]), a1);
                a2 = fmaf(__ldg(&wrow[p + 2]), __ldg(&Wp_a[(p + 2) * 128 + t]), a2);
                a3 = fmaf(__ldg(&wrow[p + 3]), __ldg(&Wp_a[(p + 3) * 128 + t]), a3);
            }
            atomicAdd(&G_MA[k * 128 + t], (a0 + a1) + (a2 + a3));
            if (t == 0) {
                float c0 = 0.f, c1 = 0.f, c2 = 0.f, c3 = 0.f;
                #pragma unroll
                for (int p = pBeg; p < pEnd; p += 4) {
                    c0 = fmaf(wrow[p + 0], bp_a[p + 0], c0);
                    c1 = fmaf(wrow[p + 1], bp_a[p + 1], c1);
                    c2 = fmaf(wrow[p + 2], bp_a[p + 2], c2);
                    c3 = fmaf(wrow[p + 3], bp_a[p + 3], c3);
                }
                atomicAdd(&G_CA[k], (c0 + c1) + (c2 + c3));
            }
        }
    }
}

// ---------------------------------------------------------------------------
// Kernel 2: node logits  out[N,KOUT] = X[N,KDIM] @ M[KOUT,KDIM].T + c
// 256 nodes/block; thread = 4 consecutive nodes x OPT outs; f32x2 inner loop.
// Per k-step: 1 LDS.128 (x quad) + OPT/2 broadcast LDS.64 (M) + 2*OPT fma2.
// ---------------------------------------------------------------------------
template <int KDIM, int KOUT, int OPT>
__device__ __forceinline__ void node_body(const float* __restrict__ X,
                                          const float* __restrict__ M,
                                          const float* __restrict__ c,
                                          float* __restrict__ out, int N,
                                          int blk, float* Xs, float* Ms) {
    constexpr int KT = 32;
    const int t = threadIdx.x;
    const int n0 = blk * 256;
    const int ng = t & 63;    // node quad id (nodes 4*ng .. 4*ng+3)
    const int og = t >> 6;    // out group (0..3)

    ull acc[4][OPT / 2];
    #pragma unroll
    for (int i = 0; i < 4; i++)
        #pragma unroll
        for (int cp = 0; cp < OPT / 2; cp++) acc[i][cp] = 0ull;

    const int sn = n0 + t;
    const bool vs = sn < N;
    const float* xrow = X + (size_t)(vs ? sn : (N - 1)) * KDIM;

    for (int j0 = 0; j0 < KDIM; j0 += KT) {
        // stage X tile transposed: Xs[j][node] for 256 nodes
        #pragma unroll
        for (int q = 0; q < 8; q++) {
            float4 v = vs ? *reinterpret_cast<const float4*>(xrow + j0 + 4 * q)
                          : make_float4(0.f, 0.f, 0.f, 0.f);
            Xs[(4 * q + 0) * 256 + t] = v.x;
            Xs[(4 * q + 1) * 256 + t] = v.y;
            Xs[(4 * q + 2) * 256 + t] = v.z;
            Xs[(4 * q + 3) * 256 + t] = v.w;
        }
        #pragma unroll
        for (int idx = t; idx < KT * KOUT; idx += 256) {
            int j = idx / KOUT, k = idx - j * KOUT;
            Ms[j * KOUT + k] = M[k * KDIM + j0 + j];
        }
        __syncthreads();
        #pragma unroll
        for (int j = 0; j < KT; j++) {
            float4 xv = *reinterpret_cast<const float4*>(&Xs[j * 256 + 4 * ng]);
            ull x0 = pk2(xv.x, xv.x);
            ull x1 = pk2(xv.y, xv.y);
            ull x2 = pk2(xv.z, xv.z);
            ull x3 = pk2(xv.w, xv.w);
            #pragma unroll
            for (int cp = 0; cp < OPT / 2; cp++) {
                ull m2 = *reinterpret_cast<const ull*>(
                    &Ms[j * KOUT + og * OPT + 2 * cp]);
                fma2(acc[0][cp], x0, m2);
                fma2(acc[1][cp], x1, m2);
                fma2(acc[2][cp], x2, m2);
                fma2(acc[3][cp], x3, m2);
            }
        }
        __syncthreads();
    }

    #pragma unroll
    for (int i = 0; i < 4; i++) {
        const int n = n0 + 4 * ng + i;
        if (n < N) {
            float r[OPT];
            #pragma unroll
            for (int cp = 0; cp < OPT / 2; cp++)
                upk(acc[i][cp], r[2 * cp], r[2 * cp + 1]);
            #pragma unroll
            for (int cc = 0; cc < OPT; cc++)
                r[cc] += __ldg(&c[og * OPT + cc]);
            #pragma unroll
            for (int v = 0; v < OPT / 4; v++)
                *reinterpret_cast<float4*>(
                    &out[(size_t)n * KOUT + og * OPT + 4 * v]) =
                    make_float4(r[4 * v], r[4 * v + 1], r[4 * v + 2],
                                r[4 * v + 3]);
        }
    }
}

__global__ void __launch_bounds__(256)
node_kernel(const float* __restrict__ xp, const float* __restrict__ xa,
            const float* __restrict__ Mp, const float* __restrict__ cp,
            const float* __restrict__ Ma, const float* __restrict__ ca,
            float* __restrict__ pL, float* __restrict__ aL,
            int Np, int Na, int npBlocks) {
    __shared__ float Xs[32 * 256];
    __shared__ float Ms[32 * 48];
    if ((int)blockIdx.x < npBlocks)
        node_body<256, 48, 12>(xp, Mp, cp, pL, Np, blockIdx.x, Xs, Ms);
    else
        node_body<128, 16, 4>(xa, Ma, ca, aL, Na, blockIdx.x - npBlocks, Xs, Ms);
}

// ---------------------------------------------------------------------------
// Kernel 3 (fused, merged edge types): 16 edges per pipeline stage.
// Lane l: edge = l>>2 (+8 for sub-batch B), k-chunk = l&3.
// ---------------------------------------------------------------------------
__global__ void __launch_bounds__(256, 2)
edge_fused_kernel(const int* __restrict__ eiW, const int* __restrict__ eiC,
                  int E,
                  const float* __restrict__ aL, const float* __restrict__ pL,
                  const float* __restrict__ A_w, const float* __restrict__ A_c,
                  float* __restrict__ out, int nbHalf) {
    __shared__ __align__(16) float4 bsh[8][2][2][32]; // [warp][buf][sub][e*4+kq]

    const bool isW = (int)blockIdx.x < nbHalf;
    const int bid = isW ? blockIdx.x : blockIdx.x - nbHalf;
    const int* ei = isW ? eiW : eiC;
    const float* srcL = isW ? aL : (pL + 16);
    const int sStride = isW ? 16 : 48;
    const float* dstL = isW ? pL : (pL + 32);
    const float* A = isW ? A_w : A_c;
    float* o = isW ? out : out + (size_t)E * 128;

    const int lane = threadIdx.x & 31;
    const int w = threadIdx.x >> 5;
    const int eSub = lane >> 2;   // edge within sub-batch (0..7)
    const int kq = lane & 3;      // float4 chunk of the 16 logits

    // A preload: lane owns output columns [4*lane, 4*lane+4) for all 16 k.
    ull aLr[16], aHr[16];
    #pragma unroll
    for (int k = 0; k < 16; k++) {
        float4 v = reinterpret_cast<const float4*>(A)[k * 32 + lane];
        aLr[k] = pk2(v.x, v.y);
        aHr[k] = pk2(v.z, v.w);
    }

    const int gw = bid * 8 + w;
    const int base = gw * 16;               // first edge of this warp's batch 0
    const int step = nbHalf * 8 * 16;       // edges consumed per iter, all warps
    if (base >= E) return;
    const int nIter = (E - base + step - 1) / step;

    float4 lgA, lgB;

    #define GATHER(t_)                                                        \
        do {                                                                  \
            int eA_ = min(base + (t_) * step + eSub, E - 1);                  \
            int eB_ = min(base + (t_) * step + eSub + 8, E - 1);              \
            int sA_ = __ldg(&ei[eA_]);                                        \
            int dA_ = __ldg(&ei[E + eA_]);                                    \
            int sB_ = __ldg(&ei[eB_]);                                        \
            int dB_ = __ldg(&ei[E + eB_]);                                    \
            float4 lsA_ = *reinterpret_cast<const float4*>(                   \
                &srcL[(size_t)sA_ * sStride + 4 * kq]);                       \
            float4 ldA_ = *reinterpret_cast<const float4*>(                   \
                &dstL[(size_t)dA_ * 48 + 4 * kq]);                            \
            float4 lsB_ = *reinterpret_cast<const float4*>(                   \
                &srcL[(size_t)sB_ * sStride + 4 * kq]);                       \
            float4 ldB_ = *reinterpret_cast<const float4*>(                   \
                &dstL[(size_t)dB_ * 48 + 4 * kq]);                            \
            lgA.x = lsA_.x + ldA_.x; lgA.y = lsA_.y + ldA_.y;                 \
            lgA.z = lsA_.z + ldA_.z; lgA.w = lsA_.w + ldA_.w;                 \
            lgB.x = lsB_.x + ldB_.x; lgB.y = lsB_.y + ldB_.y;                 \
            lgB.z = lsB_.z + ldB_.z; lgB.w = lsB_.w + ldB_.w;                 \
            lgA.x = fmaxf(lgA.x, 0.01f * lgA.x);                              \
            lgA.y = fmaxf(lgA.y, 0.01f * lgA.y);                              \
            lgA.z = fmaxf(lgA.z, 0.01f * lgA.z);                              \
            lgA.w = fmaxf(lgA.w, 0.01f * lgA.w);                              \
            lgB.x = fmaxf(lgB.x, 0.01f * lgB.x);                              \
            lgB.y = fmaxf(lgB.y, 0.01f * lgB.y);                              \
            lgB.z = fmaxf(lgB.z, 0.01f * lgB.z);                              \
            lgB.w = fmaxf(lgB.w, 0.01f * lgB.w);                              \
        } while (0)

    #define SOFTMAX_TO(buf_)                                                  \
        do {                                                                  \
            float4 exA_, exB_;                                                \
            exA_.x = __expf(lgA.x); exA_.y = __expf(lgA.y);                   \
            exA_.z = __expf(lgA.z); exA_.w = __expf(lgA.w);                   \
            exB_.x = __expf(lgB.x); exB_.y = __expf(lgB.y);                   \
            exB_.z = __expf(lgB.z); exB_.w = __expf(lgB.w);                   \
            float sA_ = (exA_.x + exA_.y) + (exA_.z + exA_.w);                \
            float sB_ = (exB_.x + exB_.y) + (exB_.z + exB_.w);                \
            sA_ += __shfl_xor_sync(0xffffffffu, sA_, 1, 4);                   \
            sB_ += __shfl_xor_sync(0xffffffffu, sB_, 1, 4);                   \
            sA_ += __shfl_xor_sync(0xffffffffu, sA_, 2, 4);                   \
            sB_ += __shfl_xor_sync(0xffffffffu, sB_, 2, 4);                   \
            float rA_ = __fdividef(1.f, sA_);                                 \
            float rB_ = __fdividef(1.f, sB_);                                 \
            exA_.x *= rA_; exA_.y *= rA_; exA_.z *= rA_; exA_.w *= rA_;       \
            exB_.x *= rB_; exB_.y *= rB_; exB_.z *= rB_; exB_.w *= rB_;       \
            bsh[w][buf_][0][lane] = exA_;                                     \
            bsh[w][buf_][1][lane] = exB_;                                     \
        } while (0)

    #define EDGE_MM(brow_, dst_)                                              \
        do {                                                                  \
            ull accL_ = 0ull, accH_ = 0ull;                                   \
            _Pragma("unroll")                                                 \
            for (int q = 0; q < 4; q++) {                                     \
                float4 bv_ = (brow_)[q];                                      \
                ull b0_ = pk2(bv_.x, bv_.x);                                  \
                ull b1_ = pk2(bv_.y, bv_.y);                                  \
                ull b2_ = pk2(bv_.z, bv_.z);                                  \
                ull b3_ = pk2(bv_.w, bv_.w);                                  \
                fma2(accL_, b0_, aLr[4 * q + 0]);                             \
                fma2(accH_, b0_, aHr[4 * q + 0]);                             \
                fma2(accL_, b1_, aLr[4 * q + 1]);                             \
                fma2(accH_, b1_, aHr[4 * q + 1]);                             \
                fma2(accL_, b2_, aLr[4 * q + 2]);                             \
                fma2(accH_, b2_, aHr[4 * q + 2]);                             \
                fma2(accL_, b3_, aLr[4 * q + 3]);                             \
                fma2(accH_, b3_, aHr[4 * q + 3]);                             \
            }                                                                 \
            st4cs(dst_, accL_, accH_);                                        \
        } while (0)

    GATHER(0);
    SOFTMAX_TO(0);
    GATHER(1);
    __syncwarp();

    for (int t = 0; t < nIter; t++) {
        const int buf = t & 1;

        SOFTMAX_TO(buf ^ 1);
        GATHER(t + 2);

        const int eb = base + t * step;
        float* obase = o + (size_t)eb * 128 + 4 * lane;
        if (eb + 16 <= E) {
            #pragma unroll
            for (int v = 0; v < 16; v++) {
                const float4* brow = &bsh[w][buf][v >> 3][(v & 7) * 4];
                EDGE_MM(brow, obase + (size_t)v * 128);
            }
        } else {
            #pragma unroll
            for (int v = 0; v < 16; v++) {
                if (eb + v < E) {
                    const float4* brow = &bsh[w][buf][v >> 3][(v & 7) * 4];
                    EDGE_MM(brow, obase + (size_t)v * 128);
                }
            }
        }
        __syncwarp();
    }
    #undef GATHER
    #undef SOFTMAX_TO
    #undef EDGE_MM
}

// ---------------------------------------------------------------------------
extern "C" void kernel_launch(void* const* d_in, const int* in_sizes, int n_in,
                              void* d_out, int out_size) {
    const float* x_paper   = (const float*)d_in[0];
    const float* x_author  = (const float*)d_in[1];
    const float* Wp_paper  = (const float*)d_in[2];
    const float* bp_paper  = (const float*)d_in[3];
    const float* Wp_author = (const float*)d_in[4];
    const float* bp_author = (const float*)d_in[5];
    const float* Ws_writes = (const float*)d_in[6];
    const float* bs_writes = (const float*)d_in[7];
    const float* A_writes  = (const float*)d_in[8];
    const float* Ws_cites  = (const float*)d_in[9];
    const float* bs_cites  = (const float*)d_in[10];
    const float* A_cites   = (const float*)d_in[11];
    const int*   ei_writes = (const int*)d_in[12];
    const int*   ei_cites  = (const int*)d_in[13];
    float* out = (float*)d_out;

    const int Np = in_sizes[0] / 256;
    const int Na = in_sizes[1] / 128;
    const int E  = in_sizes[12] / 2;

    float *fold, *pL, *aL;
    cudaGetSymbolAddress((void**)&fold, g_fold);
    cudaGetSymbolAddress((void**)&pL, g_paperL);
    cudaGetSymbolAddress((void**)&aL, g_authorL);
    float* Mp = fold;
    float* Ma = fold + 12288;
    float* cp = fold + 14336;
    float* ca = fold + 14384;

    cudaMemsetAsync(fold, 0, 14400 * sizeof(float));

    fold_kernel<<<dim3(64, 4), 256>>>(Wp_paper, bp_paper, Wp_author, bp_author,
                                      Ws_writes, bs_writes, Ws_cites, bs_cites);

    const int npB = (Np + 255) / 256;
    const int naB = (Na + 255) / 256;
    node_kernel<<<npB + naB, 256>>>(x_paper, x_author, Mp, cp, Ma, ca,
                                    pL, aL, Np, Na, npB);

    const int nbHalf = 148;  // persistent single wave: 2 CTAs/SM
    edge_fused_kernel<<<2 * nbHalf, 256>>>(ei_writes, ei_cites, E, aL, pL,
                                           A_writes, A_cites, out, nbHalf);
}